// round 2
// baseline (speedup 1.0000x reference)
#include <cuda_runtime.h>

// Normalized correlation layer, GB300 sm_103a — round 2.
// Identity: sum((a-ma)(b-mb))/(sa*sb) = (S_ab - 25*ma*mb) * (1/sa) * (1/sb).
// Pass 1: per-patch per-channel mean & rstd.
// Pass 2: raw correlation with f32x2 FMAs, correction at epilogue.
// Round-2 changes vs round 1:
//  - smem slabs store only the 12 REAL columns (static zero padding columns
//    contribute nothing -> their FMA terms are skipped entirely).
//  - a2 streamed one register at a time (no a2[16] array) -> no spills.
//  - stats read from global in epilogue (not staged in smem).
//  - smem 188KB -> 84KB  =>  2 CTAs/SM, 24 warps resident.

#define NB  16
#define NR  37
#define NC  12
#define OUTLAST 7680 // 128 * 60

typedef unsigned long long u64;

__device__ __forceinline__ u64 fma2_(u64 a, u64 b, u64 c) {
    u64 d; asm("fma.rn.f32x2 %0, %1, %2, %3;" : "=l"(d) : "l"(a), "l"(b), "l"(c)); return d;
}
__device__ __forceinline__ u64 mul2_(u64 a, u64 b) {
    u64 d; asm("mul.rn.f32x2 %0, %1, %2;" : "=l"(d) : "l"(a), "l"(b)); return d;
}
__device__ __forceinline__ u64 add2_(u64 a, u64 b) {
    u64 d; asm("add.rn.f32x2 %0, %1, %2;" : "=l"(d) : "l"(a), "l"(b)); return d;
}
__device__ __forceinline__ u64 pk2(float x, float y) {
    u64 r; asm("mov.b64 %0, {%1, %2};" : "=l"(r) : "f"(x), "f"(y)); return r;
}
__device__ __forceinline__ float2 upk2(u64 v) {
    float2 f; asm("mov.b64 {%0, %1}, %2;" : "=f"(f.x), "=f"(f.y) : "l"(v)); return f;
}

// Stats scratch. Image1: row starts 0..36. Image2: row starts 0..38.
// g_nA holds -25*mean (pre-multiplied for the epilogue fma).
__device__ float g_nA[NB * NR * NC * 128];
__device__ float g_rA[NB * NR * NC * 128];
__device__ float g_mB[NB * 39 * NC * 128];
__device__ float g_rB[NB * 39 * NC * 128];

// ---------------------------------------------------------------------------
// Pass 1: per-patch per-channel mean and rstd.
// grid.x: 0..36 -> image1 row start; 37..75 -> image2 row start (x-37).
// ---------------------------------------------------------------------------
__global__ __launch_bounds__(384) void nc_stats_kernel(
    const float* __restrict__ in1, const float* __restrict__ in2)
{
    __shared__ u64 slab[5 * 16 * 64];
    const int bx  = blockIdx.x;
    const int b   = blockIdx.y;
    const int tid = threadIdx.x;

    const bool img1 = bx < NR;
    const int  st   = img1 ? bx : bx - NR;
    const int  roff = img1 ? 2 : 4;
    const u64* inv  = (const u64*)(img1 ? in1 : in2);

    for (int i = tid; i < 5 * 16 * 64; i += 384) {
        int c = i & 63, col = (i >> 6) & 15, dr = i >> 10;
        int row = st + dr - roff;
        int cg  = col - 2;
        u64 v = 0ull;
        if ((unsigned)row < 37u && (unsigned)cg < 12u)
            v = inv[((b * 37 + row) * 12 + cg) * 64 + c];
        slab[i] = v;
    }
    __syncthreads();

    float2* gm = (float2*)(img1 ? g_nA : g_mB);
    float2* gr = (float2*)(img1 ? g_rA : g_rB);
    const int nrows = img1 ? NR : 39;
    const float msc = img1 ? -25.0f * 0.04f : 0.04f;  // img1 stores -25*mean

    for (int t = tid; t < 12 * 64; t += 384) {
        int j = t >> 6, c = t & 63;
        u64 s = 0ull, q = 0ull;
        #pragma unroll
        for (int dr = 0; dr < 5; dr++) {
            #pragma unroll
            for (int dc = 0; dc < 5; dc++) {
                u64 v = slab[(dr * 16 + j + dc) * 64 + c];
                s = add2_(s, v);
                q = fma2_(v, v, q);
            }
        }
        float2 sf = upk2(s), qf = upk2(q);
        float mx = sf.x * 0.04f, my = sf.y * 0.04f;
        float vx = qf.x * 0.04f - mx * mx;
        float vy = qf.y * 0.04f - my * my;
        int idx = ((b * nrows + st) * 12 + j) * 64 + c;
        gm[idx] = make_float2(sf.x * msc, sf.y * msc);
        gr[idx] = make_float2(rsqrtf(vx), rsqrtf(vy));
    }
}

// ---------------------------------------------------------------------------
// Pass 2: correlation. CTA per (r, b). 384 threads = 64 ch-pairs x 6 j-pairs.
// Smem: only the 12 real columns (cols are 0..11 in INPUT coords; padded
// column terms are statically zero and skipped).
// ---------------------------------------------------------------------------
#define SM1   0
#define SM2   (5 * 12 * 64)                 // 3840
#define SMTOT (SM2 + 9 * 12 * 64)           // 10752 u64 = 86016 B

__global__ __launch_bounds__(384, 2) void nc_corr_kernel(
    const float* __restrict__ in1, const float* __restrict__ in2,
    float* __restrict__ out)
{
    extern __shared__ u64 sm[];
    const int r   = blockIdx.x;
    const int b   = blockIdx.y;
    const int tid = threadIdx.x;

    const u64* in1v = (const u64*)in1;
    const u64* in2v = (const u64*)in2;

    // Image1 slab: input rows r-2..r+2, real cols 0..11.
    for (int i = tid; i < 5 * 12 * 64; i += 384) {
        int c = i & 63, col = (i >> 6) % 12, dr = i / (12 * 64);
        int row = r + dr - 2;
        u64 v = 0ull;
        if ((unsigned)row < 37u)
            v = in1v[((b * 37 + row) * 12 + col) * 64 + c];
        sm[SM1 + i] = v;
    }
    // Image2 slab: input rows r-4..r+4, real cols 0..11.
    for (int i = tid; i < 9 * 12 * 64; i += 384) {
        int c = i & 63, col = (i >> 6) % 12, dr = i / (12 * 64);
        int row = r + dr - 4;
        u64 v = 0ull;
        if ((unsigned)row < 37u)
            v = in2v[((b * 37 + row) * 12 + col) * 64 + c];
        sm[SM2 + i] = v;
    }
    __syncthreads();

    const int cp = tid & 63;       // channel pair
    const int jp = tid >> 6;       // 0..5
    const int j0 = jp << 1;

    const u64* nAv = (const u64*)g_nA;
    const u64* rAv = (const u64*)g_rA;
    const u64* mBv = (const u64*)g_mB;
    const u64* rBv = (const u64*)g_rB;

    const int giA = ((b * 37 + r) * 12 + j0) * 64 + cp;
    const u64 na0 = nAv[giA];            // -25 * mean
    const u64 na1 = nAv[giA + 64];
    const u64 ra0 = rAv[giA];
    const u64 ra1 = rAv[giA + 64];

    const int obase = ((b * 37 + r) * 12 + j0) * OUTLAST + (cp << 1) * 60;

    #pragma unroll 1
    for (int d = 0; d < 5; d++) {
        // row2[i] = i for i<=38, else i-2.
        const int sd = (r + d <= 38) ? d : d - 2;

        u64 acc0[12], acc1[12];
        #pragma unroll
        for (int t = 0; t < 12; t++) { acc0[t] = 0ull; acc1[t] = 0ull; }

        #pragma unroll 1
        for (int dr = 0; dr < 5; dr++) {
            const u64* rowA = sm + SM1 + dr * (12 * 64) + cp;
            const u64* rowB = sm + SM2 + (sd + dr) * (12 * 64) + cp;

            // a1[x] = image1 padded col j0+x  (real col j0+x-2; zero outside)
            u64 a1[6];
            #pragma unroll
            for (int x = 0; x < 6; x++) {
                int rc = j0 + x - 2;
                u64 v = 0ull;
                if ((unsigned)rc < 12u) v = rowA[rc << 6];
                a1[x] = v;
            }
            // Stream a2 over the 12 real cols; padded cols are zero -> skipped.
            #pragma unroll
            for (int x2 = 0; x2 < 12; x2++) {
                const u64 a2v = rowB[x2 << 6];
                const int px = x2 + 2;   // padded col
                #pragma unroll
                for (int dc = 0; dc < 5; dc++) {
                    const int j2 = px - dc;
                    if (j2 >= 0 && j2 < 12) {
                        acc0[j2] = fma2_(a1[dc],     a2v, acc0[j2]);
                        acc1[j2] = fma2_(a1[dc + 1], a2v, acc1[j2]);
                    }
                }
            }
        }

        // Epilogue: (S - 25*ma*mb) * ra * rb; stats from global (L1-hot).
        const int giB = ((b * 39 + (r + sd)) * 12) * 64 + cp;
        float o00[12], o01[12], o10[12], o11[12];
        #pragma unroll
        for (int j2 = 0; j2 < 12; j2++) {
            u64 mb = mBv[giB + (j2 << 6)];
            u64 rb = rBv[giB + (j2 << 6)];
            u64 rr0 = mul2_(ra0, rb);
            u64 rr1 = mul2_(ra1, rb);
            float2 v0 = upk2(mul2_(fma2_(na0, mb, acc0[j2]), rr0));
            float2 v1 = upk2(mul2_(fma2_(na1, mb, acc1[j2]), rr1));
            o00[j2] = v0.x; o01[j2] = v0.y;
            o10[j2] = v1.x; o11[j2] = v1.y;
        }
        float* p = out + obase + d * 12;
        #pragma unroll
        for (int q = 0; q < 3; q++) {
            ((float4*)(p))[q]                 = ((float4*)o00)[q];
            ((float4*)(p + 60))[q]            = ((float4*)o01)[q];
            ((float4*)(p + OUTLAST))[q]       = ((float4*)o10)[q];
            ((float4*)(p + OUTLAST + 60))[q]  = ((float4*)o11)[q];
        }
    }
}

// ---------------------------------------------------------------------------
extern "C" void kernel_launch(void* const* d_in, const int* in_sizes, int n_in,
                              void* d_out, int out_size)
{
    const float* in1 = (const float*)d_in[0];
    const float* in2 = (const float*)d_in[1];
    float* out = (float*)d_out;

    cudaFuncSetAttribute(nc_corr_kernel,
                         cudaFuncAttributeMaxDynamicSharedMemorySize,
                         SMTOT * (int)sizeof(u64));

    nc_stats_kernel<<<dim3(NR + 39, NB), 384>>>(in1, in2);
    nc_corr_kernel<<<dim3(NR, NB), 384, SMTOT * sizeof(u64)>>>(in1, in2, out);
}

// round 3
// speedup vs baseline: 1.1642x; 1.1642x over previous
#include <cuda_runtime.h>

// Normalized correlation layer, GB300 sm_103a — round 3.
// Identity: sum((a-ma)(b-mb))/(sa*sb) = (S_ab - 25*ma*mb) * (1/sa) * (1/sb).
// Round-3 change: thread = (channel-pair, single j) -> 768 threads/CTA,
// per-thread live state halved (12 acc u64). Low register pressure lets
// ptxas batch loads and hide LDS/LDG latency; round 1/2 were stall-bound
// at ~27 cyc/instr from pressure-induced load-use serialization.

#define NB  16
#define NR  37
#define OUTLAST 7680 // 128 * 60

typedef unsigned long long u64;

__device__ __forceinline__ u64 fma2_(u64 a, u64 b, u64 c) {
    u64 d; asm("fma.rn.f32x2 %0, %1, %2, %3;" : "=l"(d) : "l"(a), "l"(b), "l"(c)); return d;
}
__device__ __forceinline__ u64 mul2_(u64 a, u64 b) {
    u64 d; asm("mul.rn.f32x2 %0, %1, %2;" : "=l"(d) : "l"(a), "l"(b)); return d;
}
__device__ __forceinline__ u64 add2_(u64 a, u64 b) {
    u64 d; asm("add.rn.f32x2 %0, %1, %2;" : "=l"(d) : "l"(a), "l"(b)); return d;
}
__device__ __forceinline__ float2 upk2(u64 v) {
    float2 f; asm("mov.b64 {%0, %1}, %2;" : "=f"(f.x), "=f"(f.y) : "l"(v)); return f;
}

// Stats scratch. Image1: row starts 0..36. Image2: row starts 0..38.
// g_nA holds -25*mean (pre-multiplied for the epilogue fma).
__device__ float g_nA[NB * NR * 12 * 128];
__device__ float g_rA[NB * NR * 12 * 128];
__device__ float g_mB[NB * 39 * 12 * 128];
__device__ float g_rB[NB * 39 * 12 * 128];

// ---------------------------------------------------------------------------
// Pass 1: per-patch per-channel mean and rstd.
// grid.x: 0..36 -> image1 row start; 37..75 -> image2 row start (x-37).
// ---------------------------------------------------------------------------
__global__ __launch_bounds__(384) void nc_stats_kernel(
    const float* __restrict__ in1, const float* __restrict__ in2)
{
    __shared__ u64 slab[5 * 16 * 64];
    const int bx  = blockIdx.x;
    const int b   = blockIdx.y;
    const int tid = threadIdx.x;

    const bool img1 = bx < NR;
    const int  st   = img1 ? bx : bx - NR;
    const int  roff = img1 ? 2 : 4;
    const u64* inv  = (const u64*)(img1 ? in1 : in2);

    for (int i = tid; i < 5 * 16 * 64; i += 384) {
        int c = i & 63, col = (i >> 6) & 15, dr = i >> 10;
        int row = st + dr - roff;
        int cg  = col - 2;
        u64 v = 0ull;
        if ((unsigned)row < 37u && (unsigned)cg < 12u)
            v = inv[((b * 37 + row) * 12 + cg) * 64 + c];
        slab[i] = v;
    }
    __syncthreads();

    float2* gm = (float2*)(img1 ? g_nA : g_mB);
    float2* gr = (float2*)(img1 ? g_rA : g_rB);
    const int nrows = img1 ? NR : 39;
    const float msc = img1 ? -25.0f * 0.04f : 0.04f;  // img1 stores -25*mean

    for (int t = tid; t < 12 * 64; t += 384) {
        int j = t >> 6, c = t & 63;
        u64 s = 0ull, q = 0ull;
        #pragma unroll
        for (int dr = 0; dr < 5; dr++) {
            #pragma unroll
            for (int dc = 0; dc < 5; dc++) {
                u64 v = slab[(dr * 16 + j + dc) * 64 + c];
                s = add2_(s, v);
                q = fma2_(v, v, q);
            }
        }
        float2 sf = upk2(s), qf = upk2(q);
        float mx = sf.x * 0.04f, my = sf.y * 0.04f;
        float vx = qf.x * 0.04f - mx * mx;
        float vy = qf.y * 0.04f - my * my;
        int idx = ((b * nrows + st) * 12 + j) * 64 + c;
        gm[idx] = make_float2(sf.x * msc, sf.y * msc);
        gr[idx] = make_float2(rsqrtf(vx), rsqrtf(vy));
    }
}

// ---------------------------------------------------------------------------
// Pass 2: correlation. CTA per (r, b). 768 threads = 64 ch-pairs x 12 j.
// ---------------------------------------------------------------------------
#define SM1   0
#define SM2   (5 * 12 * 64)                 // 3840
#define SMTOT (SM2 + 9 * 12 * 64)           // 10752 u64 = 86016 B

__global__ __launch_bounds__(768, 1) void nc_corr_kernel(
    const float* __restrict__ in1, const float* __restrict__ in2,
    float* __restrict__ out)
{
    extern __shared__ u64 sm[];
    const int r   = blockIdx.x;
    const int b   = blockIdx.y;
    const int tid = threadIdx.x;

    const u64* in1v = (const u64*)in1;
    const u64* in2v = (const u64*)in2;

    // Image1 slab: input rows r-2..r+2, real cols 0..11.
    for (int i = tid; i < 5 * 12 * 64; i += 768) {
        int c = i & 63, col = (i >> 6) % 12, dr = i / (12 * 64);
        int row = r + dr - 2;
        u64 v = 0ull;
        if ((unsigned)row < 37u)
            v = in1v[((b * 37 + row) * 12 + col) * 64 + c];
        sm[SM1 + i] = v;
    }
    // Image2 slab: input rows r-4..r+4, real cols 0..11.
    for (int i = tid; i < 9 * 12 * 64; i += 768) {
        int c = i & 63, col = (i >> 6) % 12, dr = i / (12 * 64);
        int row = r + dr - 4;
        u64 v = 0ull;
        if ((unsigned)row < 37u)
            v = in2v[((b * 37 + row) * 12 + col) * 64 + c];
        sm[SM2 + i] = v;
    }
    __syncthreads();

    const int cp = tid & 63;       // channel pair: channels 2cp, 2cp+1
    const int j  = tid >> 6;       // 0..11

    const u64* nAv = (const u64*)g_nA;
    const u64* rAv = (const u64*)g_rA;
    const u64* mBv = (const u64*)g_mB;
    const u64* rBv = (const u64*)g_rB;

    const int giA = ((b * 37 + r) * 12 + j) * 64 + cp;
    const u64 na = nAv[giA];            // -25 * mean
    const u64 ra = rAv[giA];

    const int obase = ((b * 37 + r) * 12 + j) * OUTLAST + (cp << 1) * 60;

    #pragma unroll 1
    for (int d = 0; d < 5; d++) {
        // row2[i] = i for i<=38, else i-2.
        const int sd = (r + d <= 38) ? d : d - 2;

        u64 acc[12];
        #pragma unroll
        for (int t = 0; t < 12; t++) acc[t] = 0ull;

        #pragma unroll
        for (int dr = 0; dr < 5; dr++) {
            const u64* rowA = sm + SM1 + dr * (12 * 64) + cp;
            const u64* rowB = sm + SM2 + (sd + dr) * (12 * 64) + cp;

            // a1[x] = image1 padded col j+x  (real col j+x-2; zero outside)
            u64 a1[5];
            #pragma unroll
            for (int x = 0; x < 5; x++) {
                int rc = j + x - 2;
                u64 v = 0ull;
                if ((unsigned)rc < 12u) v = rowA[rc << 6];
                a1[x] = v;
            }
            // Stream a2 over the 12 real cols; padded cols are zero -> skipped.
            #pragma unroll
            for (int x2 = 0; x2 < 12; x2++) {
                const u64 a2v = rowB[x2 << 6];
                #pragma unroll
                for (int dc = 0; dc < 5; dc++) {
                    const int j2 = x2 + 2 - dc;
                    if (j2 >= 0 && j2 < 12)
                        acc[j2] = fma2_(a1[dc], a2v, acc[j2]);
                }
            }
        }

        // Epilogue: (S - 25*ma*mb) * ra * rb; stats from global (L2-hot).
        const int giB = ((b * 39 + (r + sd)) * 12) * 64 + cp;
        float o0[12], o1[12];
        #pragma unroll
        for (int j2 = 0; j2 < 12; j2++) {
            u64 mb = mBv[giB + (j2 << 6)];
            u64 rb = rBv[giB + (j2 << 6)];
            float2 v = upk2(mul2_(fma2_(na, mb, acc[j2]), mul2_(ra, rb)));
            o0[j2] = v.x; o1[j2] = v.y;
        }
        float* p = out + obase + d * 12;
        #pragma unroll
        for (int q = 0; q < 3; q++) {
            ((float4*)(p))[q]      = ((float4*)o0)[q];
            ((float4*)(p + 60))[q] = ((float4*)o1)[q];
        }
    }
}

// ---------------------------------------------------------------------------
extern "C" void kernel_launch(void* const* d_in, const int* in_sizes, int n_in,
                              void* d_out, int out_size)
{
    const float* in1 = (const float*)d_in[0];
    const float* in2 = (const float*)d_in[1];
    float* out = (float*)d_out;

    cudaFuncSetAttribute(nc_corr_kernel,
                         cudaFuncAttributeMaxDynamicSharedMemorySize,
                         SMTOT * (int)sizeof(u64));

    nc_stats_kernel<<<dim3(NR + 39, NB), 384>>>(in1, in2);
    nc_corr_kernel<<<dim3(NR, NB), 768, SMTOT * sizeof(u64)>>>(in1, in2, out);
}